// round 13
// baseline (speedup 1.0000x reference)
#include <cuda_runtime.h>
#include <cuda_fp16.h>
#include <cstdint>

#define TDIM 4096
#define NELEM (TDIM * TDIM)
#define KITERS 64            // 4096 / 64
#define STAGE_BYTES 65536    // 4 operand tiles x 128 rows x 128B
#define GEMM_SMEM (3 * STAGE_BYTES + 1024)
#define ATT_SCALE 0.015625f  // 1/sqrt(4096)

// ------------------------- scratch (__device__ globals) ---------------------
__device__ __half g_XH[NELEM],  g_XL[NELEM];
__device__ __half g_WTH[NELEM], g_WTL[NELEM];
__device__ __half g_QH[NELEM],  g_QL[NELEM];
__device__ __half g_KH[NELEM],  g_KL[NELEM];
__device__ __half g_VH[NELEM],  g_VL[NELEM];
__device__ __half g_PH[NELEM];
__device__ float g_S[NELEM];

// ------------------------------ helpers -------------------------------------
__device__ __forceinline__ uint32_t smem_to_u32(const void* p) {
    uint32_t a;
    asm("{ .reg .u64 t; cvta.to.shared.u64 t, %1; cvt.u32.u64 %0, t; }"
        : "=r"(a) : "l"(p));
    return a;
}
#define SMEM_SWIZZLE_128B(b) ((b) ^ (((b) >> 3) & 0x70))

__device__ __forceinline__ void ldsm4(uint32_t* r, uint32_t addr) {
    asm volatile("ldmatrix.sync.aligned.m8n8.x4.shared.b16 {%0,%1,%2,%3}, [%4];"
                 : "=r"(r[0]), "=r"(r[1]), "=r"(r[2]), "=r"(r[3]) : "r"(addr));
}
__device__ __forceinline__ void mma16816(float* c, const uint32_t* a, const uint32_t* b) {
    asm volatile("mma.sync.aligned.m16n8k16.row.col.f32.f16.f16.f32 "
                 "{%0,%1,%2,%3}, {%4,%5,%6,%7}, {%8,%9}, {%0,%1,%2,%3};"
                 : "+f"(c[0]), "+f"(c[1]), "+f"(c[2]), "+f"(c[3])
                 : "r"(a[0]), "r"(a[1]), "r"(a[2]), "r"(a[3]), "r"(b[0]), "r"(b[1]));
}

// --------------------------- fp32 -> fp16 hi/lo -----------------------------
__device__ __forceinline__ void split1(float v, unsigned short& h, unsigned short& l) {
    __half hb = __float2half_rn(v);
    __half lb = __float2half_rn(v - __half2float(hb));
    h = __half_as_ushort(hb);
    l = __half_as_ushort(lb);
}

// -------------------------- split (no transpose) ----------------------------
__global__ void __launch_bounds__(256)
split_kernel(const float4* __restrict__ in,
             __half* __restrict__ oh, __half* __restrict__ ol) {
    size_t i = (size_t)blockIdx.x * 256 + threadIdx.x;
    float4 v = in[i];
    unsigned short h0, h1, h2, h3, l0, l1, l2, l3;
    split1(v.x, h0, l0); split1(v.y, h1, l1); split1(v.z, h2, l2); split1(v.w, h3, l3);
    uint2 hp, lp;
    hp.x = (uint32_t)h0 | ((uint32_t)h1 << 16); hp.y = (uint32_t)h2 | ((uint32_t)h3 << 16);
    lp.x = (uint32_t)l0 | ((uint32_t)l1 << 16); lp.y = (uint32_t)l2 | ((uint32_t)l3 << 16);
    reinterpret_cast<uint2*>(oh)[i] = hp;
    reinterpret_cast<uint2*>(ol)[i] = lp;
}

// ---------------------------- transpose + split -----------------------------
__global__ void __launch_bounds__(256)
transpose_split_kernel(const float* __restrict__ in,
                       __half* __restrict__ oh, __half* __restrict__ ol) {
    __shared__ float t[32][33];
    int bx = blockIdx.x * 32, by = blockIdx.y * 32;
    int tx = threadIdx.x & 31, ty = threadIdx.x >> 5;
#pragma unroll
    for (int i = 0; i < 4; ++i)
        t[ty + 8 * i][tx] = in[(size_t)(by + ty + 8 * i) * TDIM + bx + tx];
    __syncthreads();
#pragma unroll
    for (int i = 0; i < 4; ++i) {
        float v = t[tx][ty + 8 * i];   // out[bx+ty+8i][by+tx] = in[by+tx][bx+ty+8i]
        unsigned short h, l;
        split1(v, h, l);
        size_t o = (size_t)(bx + ty + 8 * i) * TDIM + by + tx;
        oh[o] = __ushort_as_half(h);
        ol[o] = __ushort_as_half(l);
    }
}

// ------------------------- row softmax -> fp16 ------------------------------
__global__ void __launch_bounds__(256)
softmax_kernel(const float* __restrict__ S, __half* __restrict__ ph) {
    __shared__ float red[8];
    int tid = threadIdx.x, wid = tid >> 5, lid = tid & 31;
    const float4* src = reinterpret_cast<const float4*>(S + (size_t)blockIdx.x * TDIM);
    float4 v[4];
    float mx = -3.0e38f;
#pragma unroll
    for (int i = 0; i < 4; ++i) {
        v[i] = src[tid + i * 256];
        mx = fmaxf(mx, fmaxf(fmaxf(v[i].x, v[i].y), fmaxf(v[i].z, v[i].w)));
    }
#pragma unroll
    for (int o = 16; o; o >>= 1) mx = fmaxf(mx, __shfl_xor_sync(0xFFFFFFFFu, mx, o));
    if (lid == 0) red[wid] = mx;
    __syncthreads();
    mx = red[0];
#pragma unroll
    for (int i = 1; i < 8; ++i) mx = fmaxf(mx, red[i]);
    __syncthreads();
    float sum = 0.0f;
#pragma unroll
    for (int i = 0; i < 4; ++i) {
        v[i].x = __expf(v[i].x - mx); v[i].y = __expf(v[i].y - mx);
        v[i].z = __expf(v[i].z - mx); v[i].w = __expf(v[i].w - mx);
        sum += (v[i].x + v[i].y) + (v[i].z + v[i].w);
    }
#pragma unroll
    for (int o = 16; o; o >>= 1) sum += __shfl_xor_sync(0xFFFFFFFFu, sum, o);
    if (lid == 0) red[wid] = sum;
    __syncthreads();
    sum = red[0];
#pragma unroll
    for (int i = 1; i < 8; ++i) sum += red[i];
    float inv = __frcp_rn(sum);
    uint2* oph = reinterpret_cast<uint2*>(ph + (size_t)blockIdx.x * TDIM);
#pragma unroll
    for (int i = 0; i < 4; ++i) {
        __half h0 = __float2half_rn(v[i].x * inv), h1 = __float2half_rn(v[i].y * inv);
        __half h2 = __float2half_rn(v[i].z * inv), h3 = __float2half_rn(v[i].w * inv);
        uint2 hp;
        hp.x = (uint32_t)__half_as_ushort(h0) | ((uint32_t)__half_as_ushort(h1) << 16);
        hp.y = (uint32_t)__half_as_ushort(h2) | ((uint32_t)__half_as_ushort(h3) << 16);
        oph[tid + i * 256] = hp;
    }
}

// --------------------------- split-fp16 GEMM (mma.sync) ---------------------
// NPROD=3: D = Ah*Bh + Ah*Bl + Al*Bh  (err ~2^-22)
// NPROD=1: D = Ah*Bh                  (err ~2^-11)
// Operands K-major [4096][4096] fp16. CTA tile 128x128, K-chunk 64, 3 stages.
template <int NPROD>
__device__ __forceinline__ void load_stage(
    uint32_t tb, int s,
    const __half* Ah, const __half* Al,
    const __half* Bh, const __half* Bl,
    int m0, int n0, int kit, int tid) {
    int k0 = kit * 64;
    uint32_t sbase = tb + s * STAGE_BYTES;
    const int NOPS = (NPROD == 3) ? 4 : 2;
#pragma unroll
    for (int i = 0; i < 4 * NOPS; ++i) {
        int cid = tid + i * 256;
        int opi = cid >> 10;                          // const per unrolled i
        int op = (NPROD == 3) ? opi : (opi * 2);      // {0,1}->{0,2} when NPROD==1
        int rem = cid & 1023;
        int r = rem >> 3;
        int c = rem & 7;
        const __half* base = (op == 0) ? Ah : (op == 1) ? Al : (op == 2) ? Bh : Bl;
        int rb = (op < 2) ? m0 : n0;
        const char* src = (const char*)(base + (size_t)(rb + r) * TDIM + k0) + c * 16;
        uint32_t dst = sbase + op * 16384 + SMEM_SWIZZLE_128B((uint32_t)(r * 128 + c * 16));
        asm volatile("cp.async.cg.shared.global [%0], [%1], 16;" :: "r"(dst), "l"(src));
    }
}

template <int NPROD>
__global__ void __launch_bounds__(256, 1)
gemm128_kernel(const __half* __restrict__ Ah, const __half* __restrict__ Al,
               const __half* __restrict__ Bh, const __half* __restrict__ Bl,
               const float* __restrict__ bias, float scale,
               float* __restrict__ out_f,
               __half* __restrict__ oh, __half* __restrict__ ol) {
    extern __shared__ char smem[];
    uint32_t tb = (smem_to_u32(smem) + 1023u) & ~1023u;   // 1KB-aligned (SW128)
    int tid = threadIdx.x, lane = tid & 31, w = tid >> 5;
    int wm = w & 1, wn = w >> 1;                           // warp tile 64(m) x 32(n)
    int m0 = blockIdx.y * 128, n0 = blockIdx.x * 128;

    // per-lane ldmatrix address components (swizzle folds to constant XOR)
    int lr = lane & 7;
    int lxor = lr * 16;
    int a_row = wm * 64 + ((lane >> 3) & 1) * 8 + lr;      // +mi*16 later
    int a_kx  = ((lane >> 4) & 1) * 16;
    int b_row = wn * 32 + ((lane >> 4) & 1) * 8 + lr;      // +pair*16 later
    int b_kx  = ((lane >> 3) & 1) * 16;

    float acc[4][4][4];
#pragma unroll
    for (int mi = 0; mi < 4; ++mi)
#pragma unroll
        for (int ni = 0; ni < 4; ++ni)
#pragma unroll
            for (int c = 0; c < 4; ++c) acc[mi][ni][c] = 0.0f;

    // prologue: fill 2 of 3 stages
#pragma unroll
    for (int p = 0; p < 2; ++p) {
        load_stage<NPROD>(tb, p, Ah, Al, Bh, Bl, m0, n0, p, tid);
        asm volatile("cp.async.commit_group;" ::: "memory");
    }

    for (int it = 0; it < KITERS; ++it) {
        if (it == KITERS - 1) asm volatile("cp.async.wait_group 0;" ::: "memory");
        else                  asm volatile("cp.async.wait_group 1;" ::: "memory");
        // single barrier: proves every warp finished the previous chunk's reads
        // (so its buffer is refillable) and has completed its own wait_group.
        __syncthreads();
        if (it + 2 < KITERS) {
            load_stage<NPROD>(tb, (it + 2) % 3, Ah, Al, Bh, Bl, m0, n0, it + 2, tid);
            asm volatile("cp.async.commit_group;" ::: "memory");
        }
        uint32_t sbase = tb + (uint32_t)(it % 3) * STAGE_BYTES;
#pragma unroll
        for (int ks = 0; ks < 4; ++ks) {
            uint32_t aH[4][4], aL[4][4], bH[2][4], bL[2][4];
#pragma unroll
            for (int mi = 0; mi < 4; ++mi) {
                uint32_t off = (uint32_t)((a_row + mi * 16) * 128 + ((ks * 32 + a_kx) ^ lxor));
                ldsm4(aH[mi], sbase + off);
                if (NPROD == 3) ldsm4(aL[mi], sbase + 16384u + off);
            }
#pragma unroll
            for (int p = 0; p < 2; ++p) {
                uint32_t off = (uint32_t)((b_row + p * 16) * 128 + ((ks * 32 + b_kx) ^ lxor));
                ldsm4(bH[p], sbase + 32768u + off);
                if (NPROD == 3) ldsm4(bL[p], sbase + 49152u + off);
            }
#pragma unroll
            for (int mi = 0; mi < 4; ++mi)
#pragma unroll
                for (int ni = 0; ni < 4; ++ni) {
                    const uint32_t* fh = &bH[ni >> 1][(ni & 1) * 2];
                    mma16816(acc[mi][ni], aH[mi], fh);
                    if (NPROD == 3) {
                        const uint32_t* fl = &bL[ni >> 1][(ni & 1) * 2];
                        mma16816(acc[mi][ni], aH[mi], fl);
                        mma16816(acc[mi][ni], aL[mi], fh);
                    }
                }
        }
    }

    // epilogue: c0,c1 -> (row, col..col+1); c2,c3 -> (row+8, col..col+1)
    int er = lane >> 2, ec = (lane & 3) * 2;
    int m_base = m0 + wm * 64, n_base = n0 + wn * 32;
#pragma unroll
    for (int mi = 0; mi < 4; ++mi)
#pragma unroll
        for (int ni = 0; ni < 4; ++ni) {
            float* c = acc[mi][ni];
            int m = m_base + mi * 16 + er;
            int n = n_base + ni * 8 + ec;
            if (out_f != nullptr) {
                float2 v0 = { c[0] * scale, c[1] * scale };
                float2 v1 = { c[2] * scale, c[3] * scale };
                *reinterpret_cast<float2*>(out_f + (size_t)m * TDIM + n) = v0;
                *reinterpret_cast<float2*>(out_f + (size_t)(m + 8) * TDIM + n) = v1;
            } else {
                float b0 = bias[n], b1 = bias[n + 1];
                unsigned short h0, l0, h1, l1;
                split1(c[0] + b0, h0, l0);
                split1(c[1] + b1, h1, l1);
                *reinterpret_cast<uint32_t*>(oh + (size_t)m * TDIM + n) =
                    (uint32_t)h0 | ((uint32_t)h1 << 16);
                *reinterpret_cast<uint32_t*>(ol + (size_t)m * TDIM + n) =
                    (uint32_t)l0 | ((uint32_t)l1 << 16);
                split1(c[2] + b0, h0, l0);
                split1(c[3] + b1, h1, l1);
                *reinterpret_cast<uint32_t*>(oh + (size_t)(m + 8) * TDIM + n) =
                    (uint32_t)h0 | ((uint32_t)h1 << 16);
                *reinterpret_cast<uint32_t*>(ol + (size_t)(m + 8) * TDIM + n) =
                    (uint32_t)l0 | ((uint32_t)l1 << 16);
            }
        }
}

// -------------------------------- launcher ----------------------------------
extern "C" void kernel_launch(void* const* d_in, const int* in_sizes, int n_in,
                              void* d_out, int out_size) {
    (void)in_sizes; (void)n_in; (void)out_size;
    const float* x  = (const float*)d_in[0];
    const float* Wq = (const float*)d_in[1];
    const float* bq = (const float*)d_in[2];
    const float* Wk = (const float*)d_in[3];
    const float* bk = (const float*)d_in[4];
    const float* Wv = (const float*)d_in[5];
    const float* bv = (const float*)d_in[6];
    float* out = (float*)d_out;

    cudaFuncSetAttribute(gemm128_kernel<3>,
                         cudaFuncAttributeMaxDynamicSharedMemorySize, GEMM_SMEM);
    cudaFuncSetAttribute(gemm128_kernel<1>,
                         cudaFuncAttributeMaxDynamicSharedMemorySize, GEMM_SMEM);

    __half *pXH, *pXL, *pWTH, *pWTL, *pQH, *pQL, *pKH, *pKL, *pVH, *pVL, *pPH;
    float* pS;
    cudaGetSymbolAddress((void**)&pXH, g_XH);   cudaGetSymbolAddress((void**)&pXL, g_XL);
    cudaGetSymbolAddress((void**)&pWTH, g_WTH); cudaGetSymbolAddress((void**)&pWTL, g_WTL);
    cudaGetSymbolAddress((void**)&pQH, g_QH);   cudaGetSymbolAddress((void**)&pQL, g_QL);
    cudaGetSymbolAddress((void**)&pKH, g_KH);   cudaGetSymbolAddress((void**)&pKL, g_KL);
    cudaGetSymbolAddress((void**)&pVH, g_VH);   cudaGetSymbolAddress((void**)&pVL, g_VL);
    cudaGetSymbolAddress((void**)&pPH, g_PH);
    cudaGetSymbolAddress((void**)&pS, g_S);

    dim3 tgrid(128, 128);
    dim3 ggrid(32, 32);

    // x -> hi/lo (already K-major for projections)
    split_kernel<<<NELEM / 1024, 256>>>((const float4*)x, pXH, pXL);

    // q = x @ Wq + bq   (B = Wq^T, K-major)
    transpose_split_kernel<<<tgrid, 256>>>(Wq, pWTH, pWTL);
    gemm128_kernel<3><<<ggrid, 256, GEMM_SMEM>>>(pXH, pXL, pWTH, pWTL, bq, 1.0f,
                                                 nullptr, pQH, pQL);
    // k = x @ Wk + bk
    transpose_split_kernel<<<tgrid, 256>>>(Wk, pWTH, pWTL);
    gemm128_kernel<3><<<ggrid, 256, GEMM_SMEM>>>(pXH, pXL, pWTH, pWTL, bk, 1.0f,
                                                 nullptr, pKH, pKL);
    // v = x @ Wv + bv   (row-major [t][d]; final GEMM contracts over columns)
    transpose_split_kernel<<<tgrid, 256>>>(Wv, pWTH, pWTL);
    gemm128_kernel<3><<<ggrid, 256, GEMM_SMEM>>>(pXH, pXL, pWTH, pWTL, bv, 1.0f,
                                                 nullptr, pVH, pVL);
    // scores = (q @ k^T) * 1/sqrt(d) -> fp32 g_S
    gemm128_kernel<3><<<ggrid, 256, GEMM_SMEM>>>(pQH, pQL, pKH, pKL, nullptr, ATT_SCALE,
                                                 pS, nullptr, nullptr);
    // P = softmax(scores, rows) -> fp16
    softmax_kernel<<<TDIM, 256>>>(pS, pPH);
    // out[i][j] = sum_m P[i][m] * v[j][m]   (plain fp16, 1 product)
    gemm128_kernel<1><<<ggrid, 256, GEMM_SMEM>>>(pPH, nullptr, pVH, nullptr, nullptr, 1.0f,
                                                 out, nullptr, nullptr);
}

// round 14
// speedup vs baseline: 1.0646x; 1.0646x over previous
#include <cuda_runtime.h>
#include <cuda_fp16.h>
#include <cstdint>

#define TDIM 4096
#define NELEM (TDIM * TDIM)
#define KITERS 64            // 4096 / 64
#define STAGE_BYTES 65536    // 4 operand tiles x 128 rows x 128B
#define GEMM_SMEM (3 * STAGE_BYTES + 1024)
#define ATT_SCALE 0.015625f  // 1/sqrt(4096)

// ------------------------- scratch (__device__ globals) ---------------------
__device__ __half g_XH[NELEM],  g_XL[NELEM];
__device__ __half g_WTH[NELEM], g_WTL[NELEM];
__device__ __half g_QH[NELEM],  g_QL[NELEM];
__device__ __half g_KH[NELEM],  g_KL[NELEM];
__device__ __half g_VH[NELEM],  g_VL[NELEM];
__device__ __half g_PH[NELEM];
__device__ float g_S[NELEM];

// ------------------------------ helpers -------------------------------------
__device__ __forceinline__ uint32_t smem_to_u32(const void* p) {
    uint32_t a;
    asm("{ .reg .u64 t; cvta.to.shared.u64 t, %1; cvt.u32.u64 %0, t; }"
        : "=r"(a) : "l"(p));
    return a;
}
#define SMEM_SWIZZLE_128B(b) ((b) ^ (((b) >> 3) & 0x70))

__device__ __forceinline__ void ldsm4(uint32_t* r, uint32_t addr) {
    asm volatile("ldmatrix.sync.aligned.m8n8.x4.shared.b16 {%0,%1,%2,%3}, [%4];"
                 : "=r"(r[0]), "=r"(r[1]), "=r"(r[2]), "=r"(r[3]) : "r"(addr));
}
__device__ __forceinline__ void mma16816(float* c, const uint32_t* a, const uint32_t* b) {
    asm volatile("mma.sync.aligned.m16n8k16.row.col.f32.f16.f16.f32 "
                 "{%0,%1,%2,%3}, {%4,%5,%6,%7}, {%8,%9}, {%0,%1,%2,%3};"
                 : "+f"(c[0]), "+f"(c[1]), "+f"(c[2]), "+f"(c[3])
                 : "r"(a[0]), "r"(a[1]), "r"(a[2]), "r"(a[3]), "r"(b[0]), "r"(b[1]));
}

// --------------------------- fp32 -> fp16 hi/lo -----------------------------
__device__ __forceinline__ void split1(float v, unsigned short& h, unsigned short& l) {
    __half hb = __float2half_rn(v);
    __half lb = __float2half_rn(v - __half2float(hb));
    h = __half_as_ushort(hb);
    l = __half_as_ushort(lb);
}

// -------------------------- split (no transpose) ----------------------------
__global__ void __launch_bounds__(256)
split_kernel(const float4* __restrict__ in,
             __half* __restrict__ oh, __half* __restrict__ ol) {
    size_t i = (size_t)blockIdx.x * 256 + threadIdx.x;
    float4 v = in[i];
    unsigned short h0, h1, h2, h3, l0, l1, l2, l3;
    split1(v.x, h0, l0); split1(v.y, h1, l1); split1(v.z, h2, l2); split1(v.w, h3, l3);
    uint2 hp, lp;
    hp.x = (uint32_t)h0 | ((uint32_t)h1 << 16); hp.y = (uint32_t)h2 | ((uint32_t)h3 << 16);
    lp.x = (uint32_t)l0 | ((uint32_t)l1 << 16); lp.y = (uint32_t)l2 | ((uint32_t)l3 << 16);
    reinterpret_cast<uint2*>(oh)[i] = hp;
    reinterpret_cast<uint2*>(ol)[i] = lp;
}

// ---------------------------- transpose + split -----------------------------
__global__ void __launch_bounds__(256)
transpose_split_kernel(const float* __restrict__ in,
                       __half* __restrict__ oh, __half* __restrict__ ol) {
    __shared__ float t[32][33];
    int bx = blockIdx.x * 32, by = blockIdx.y * 32;
    int tx = threadIdx.x & 31, ty = threadIdx.x >> 5;
#pragma unroll
    for (int i = 0; i < 4; ++i)
        t[ty + 8 * i][tx] = in[(size_t)(by + ty + 8 * i) * TDIM + bx + tx];
    __syncthreads();
#pragma unroll
    for (int i = 0; i < 4; ++i) {
        float v = t[tx][ty + 8 * i];   // out[bx+ty+8i][by+tx] = in[by+tx][bx+ty+8i]
        unsigned short h, l;
        split1(v, h, l);
        size_t o = (size_t)(bx + ty + 8 * i) * TDIM + by + tx;
        oh[o] = __ushort_as_half(h);
        ol[o] = __ushort_as_half(l);
    }
}

// ------------------------- row softmax -> fp16 ------------------------------
__global__ void __launch_bounds__(256)
softmax_kernel(const float* __restrict__ S, __half* __restrict__ ph) {
    __shared__ float red[8];
    int tid = threadIdx.x, wid = tid >> 5, lid = tid & 31;
    const float4* src = reinterpret_cast<const float4*>(S + (size_t)blockIdx.x * TDIM);
    float4 v[4];
    float mx = -3.0e38f;
#pragma unroll
    for (int i = 0; i < 4; ++i) {
        v[i] = src[tid + i * 256];
        mx = fmaxf(mx, fmaxf(fmaxf(v[i].x, v[i].y), fmaxf(v[i].z, v[i].w)));
    }
#pragma unroll
    for (int o = 16; o; o >>= 1) mx = fmaxf(mx, __shfl_xor_sync(0xFFFFFFFFu, mx, o));
    if (lid == 0) red[wid] = mx;
    __syncthreads();
    mx = red[0];
#pragma unroll
    for (int i = 1; i < 8; ++i) mx = fmaxf(mx, red[i]);
    __syncthreads();
    float sum = 0.0f;
#pragma unroll
    for (int i = 0; i < 4; ++i) {
        v[i].x = __expf(v[i].x - mx); v[i].y = __expf(v[i].y - mx);
        v[i].z = __expf(v[i].z - mx); v[i].w = __expf(v[i].w - mx);
        sum += (v[i].x + v[i].y) + (v[i].z + v[i].w);
    }
#pragma unroll
    for (int o = 16; o; o >>= 1) sum += __shfl_xor_sync(0xFFFFFFFFu, sum, o);
    if (lid == 0) red[wid] = sum;
    __syncthreads();
    sum = red[0];
#pragma unroll
    for (int i = 1; i < 8; ++i) sum += red[i];
    float inv = __frcp_rn(sum);
    uint2* oph = reinterpret_cast<uint2*>(ph + (size_t)blockIdx.x * TDIM);
#pragma unroll
    for (int i = 0; i < 4; ++i) {
        __half h0 = __float2half_rn(v[i].x * inv), h1 = __float2half_rn(v[i].y * inv);
        __half h2 = __float2half_rn(v[i].z * inv), h3 = __float2half_rn(v[i].w * inv);
        uint2 hp;
        hp.x = (uint32_t)__half_as_ushort(h0) | ((uint32_t)__half_as_ushort(h1) << 16);
        hp.y = (uint32_t)__half_as_ushort(h2) | ((uint32_t)__half_as_ushort(h3) << 16);
        oph[tid + i * 256] = hp;
    }
}

// --------------------------- split-fp16 GEMM (mma.sync) ---------------------
// NPROD=3: D = Ah*Bh + Ah*Bl + Al*Bh  (err ~2^-22)
// NPROD=1: D = Ah*Bh                  (err ~2^-11)
// Operands K-major [4096][4096] fp16. CTA tile 128x128, K-chunk 64, 3 stages.
// cp.async issue is sliced into quarters and interleaved with the MMA loop.
template <int NPROD>
__device__ __forceinline__ void load_quarter(
    uint32_t tb, int s,
    const __half* Ah, const __half* Al,
    const __half* Bh, const __half* Bl,
    int m0, int n0, int kit, int tid, int q) {
    int k0 = kit * 64;
    uint32_t sbase = tb + s * STAGE_BYTES;
    const int PER = (NPROD == 3) ? 4 : 2;   // 16 or 8 total, split in 4 quarters
#pragma unroll
    for (int j = 0; j < PER; ++j) {
        int i = q * PER + j;
        int cid = tid + i * 256;
        int opi = cid >> 10;                          // const per unrolled i
        int op = (NPROD == 3) ? opi : (opi * 2);      // {0,1}->{0,2} when NPROD==1
        int rem = cid & 1023;
        int r = rem >> 3;
        int c = rem & 7;
        const __half* base = (op == 0) ? Ah : (op == 1) ? Al : (op == 2) ? Bh : Bl;
        int rb = (op < 2) ? m0 : n0;
        const char* src = (const char*)(base + (size_t)(rb + r) * TDIM + k0) + c * 16;
        uint32_t dst = sbase + op * 16384 + SMEM_SWIZZLE_128B((uint32_t)(r * 128 + c * 16));
        asm volatile("cp.async.cg.shared.global [%0], [%1], 16;" :: "r"(dst), "l"(src));
    }
}

template <int NPROD>
__global__ void __launch_bounds__(256, 1)
gemm128_kernel(const __half* __restrict__ Ah, const __half* __restrict__ Al,
               const __half* __restrict__ Bh, const __half* __restrict__ Bl,
               const float* __restrict__ bias, float scale,
               float* __restrict__ out_f,
               __half* __restrict__ oh, __half* __restrict__ ol) {
    extern __shared__ char smem[];
    uint32_t tb = (smem_to_u32(smem) + 1023u) & ~1023u;   // 1KB-aligned (SW128)
    int tid = threadIdx.x, lane = tid & 31, w = tid >> 5;
    int wm = w & 1, wn = w >> 1;                           // warp tile 64(m) x 32(n)
    int m0 = blockIdx.y * 128, n0 = blockIdx.x * 128;

    // per-lane ldmatrix address components (swizzle folds to constant XOR)
    int lr = lane & 7;
    int lxor = lr * 16;
    int a_row = wm * 64 + ((lane >> 3) & 1) * 8 + lr;      // +mi*16 later
    int a_kx  = ((lane >> 4) & 1) * 16;
    int b_row = wn * 32 + ((lane >> 4) & 1) * 8 + lr;      // +pair*16 later
    int b_kx  = ((lane >> 3) & 1) * 16;

    float acc[4][4][4];
#pragma unroll
    for (int mi = 0; mi < 4; ++mi)
#pragma unroll
        for (int ni = 0; ni < 4; ++ni)
#pragma unroll
            for (int c = 0; c < 4; ++c) acc[mi][ni][c] = 0.0f;

    // double-buffered fragments across ks-steps
    uint32_t aH[2][4][4], aL[2][4][4], bH[2][2][4], bL[2][2][4];

    // prologue: fill 2 of 3 stages
#pragma unroll
    for (int p = 0; p < 2; ++p) {
#pragma unroll
        for (int q = 0; q < 4; ++q)
            load_quarter<NPROD>(tb, p, Ah, Al, Bh, Bl, m0, n0, p, tid, q);
        asm volatile("cp.async.commit_group;" ::: "memory");
    }

    for (int it = 0; it < KITERS; ++it) {
        if (it == KITERS - 1) asm volatile("cp.async.wait_group 0;" ::: "memory");
        else                  asm volatile("cp.async.wait_group 1;" ::: "memory");
        // single barrier: proves every warp finished the previous chunk's reads
        // (so its buffer is refillable) and has completed its own wait_group.
        __syncthreads();
        uint32_t sbase = tb + (uint32_t)(it % 3) * STAGE_BYTES;
        bool pre = (it + 2 < KITERS);
        int ps = (it + 2) % 3;

        // fragment loader for one ks-step into buffer `buf`
        auto load_frags = [&](int ks, int buf) {
#pragma unroll
            for (int mi = 0; mi < 4; ++mi) {
                uint32_t off = (uint32_t)((a_row + mi * 16) * 128 + ((ks * 32 + a_kx) ^ lxor));
                ldsm4(aH[buf][mi], sbase + off);
                if (NPROD == 3) ldsm4(aL[buf][mi], sbase + 16384u + off);
            }
#pragma unroll
            for (int p = 0; p < 2; ++p) {
                uint32_t off = (uint32_t)((b_row + p * 16) * 128 + ((ks * 32 + b_kx) ^ lxor));
                ldsm4(bH[buf][p], sbase + 32768u + off);
                if (NPROD == 3) ldsm4(bL[buf][p], sbase + 49152u + off);
            }
        };

        // fragments for ks=0 first, before any cp.async issue
        load_frags(0, 0);

#pragma unroll
        for (int ks = 0; ks < 4; ++ks) {
            int cur = ks & 1;
            // interleave 1/4 of next chunk's cp.async issue with this ks-step
            if (pre) load_quarter<NPROD>(tb, ps, Ah, Al, Bh, Bl, m0, n0, it + 2, tid, ks);
            // prefetch next ks-step's fragments before this step's MMAs
            if (ks < 3) load_frags(ks + 1, cur ^ 1);
#pragma unroll
            for (int mi = 0; mi < 4; ++mi)
#pragma unroll
                for (int ni = 0; ni < 4; ++ni) {
                    const uint32_t* fh = &bH[cur][ni >> 1][(ni & 1) * 2];
                    mma16816(acc[mi][ni], aH[cur][mi], fh);
                    if (NPROD == 3) {
                        const uint32_t* fl = &bL[cur][ni >> 1][(ni & 1) * 2];
                        mma16816(acc[mi][ni], aH[cur][mi], fl);
                        mma16816(acc[mi][ni], aL[cur][mi], fh);
                    }
                }
        }
        if (pre) asm volatile("cp.async.commit_group;" ::: "memory");
    }

    // epilogue: c0,c1 -> (row, col..col+1); c2,c3 -> (row+8, col..col+1)
    int er = lane >> 2, ec = (lane & 3) * 2;
    int m_base = m0 + wm * 64, n_base = n0 + wn * 32;
#pragma unroll
    for (int mi = 0; mi < 4; ++mi)
#pragma unroll
        for (int ni = 0; ni < 4; ++ni) {
            float* c = acc[mi][ni];
            int m = m_base + mi * 16 + er;
            int n = n_base + ni * 8 + ec;
            if (out_f != nullptr) {
                float2 v0 = { c[0] * scale, c[1] * scale };
                float2 v1 = { c[2] * scale, c[3] * scale };
                *reinterpret_cast<float2*>(out_f + (size_t)m * TDIM + n) = v0;
                *reinterpret_cast<float2*>(out_f + (size_t)(m + 8) * TDIM + n) = v1;
            } else {
                float b0 = bias[n], b1 = bias[n + 1];
                unsigned short h0, l0, h1, l1;
                split1(c[0] + b0, h0, l0);
                split1(c[1] + b1, h1, l1);
                *reinterpret_cast<uint32_t*>(oh + (size_t)m * TDIM + n) =
                    (uint32_t)h0 | ((uint32_t)h1 << 16);
                *reinterpret_cast<uint32_t*>(ol + (size_t)m * TDIM + n) =
                    (uint32_t)l0 | ((uint32_t)l1 << 16);
                split1(c[2] + b0, h0, l0);
                split1(c[3] + b1, h1, l1);
                *reinterpret_cast<uint32_t*>(oh + (size_t)(m + 8) * TDIM + n) =
                    (uint32_t)h0 | ((uint32_t)h1 << 16);
                *reinterpret_cast<uint32_t*>(ol + (size_t)(m + 8) * TDIM + n) =
                    (uint32_t)l0 | ((uint32_t)l1 << 16);
            }
        }
}

// -------------------------------- launcher ----------------------------------
extern "C" void kernel_launch(void* const* d_in, const int* in_sizes, int n_in,
                              void* d_out, int out_size) {
    (void)in_sizes; (void)n_in; (void)out_size;
    const float* x  = (const float*)d_in[0];
    const float* Wq = (const float*)d_in[1];
    const float* bq = (const float*)d_in[2];
    const float* Wk = (const float*)d_in[3];
    const float* bk = (const float*)d_in[4];
    const float* Wv = (const float*)d_in[5];
    const float* bv = (const float*)d_in[6];
    float* out = (float*)d_out;

    cudaFuncSetAttribute(gemm128_kernel<3>,
                         cudaFuncAttributeMaxDynamicSharedMemorySize, GEMM_SMEM);
    cudaFuncSetAttribute(gemm128_kernel<1>,
                         cudaFuncAttributeMaxDynamicSharedMemorySize, GEMM_SMEM);

    __half *pXH, *pXL, *pWTH, *pWTL, *pQH, *pQL, *pKH, *pKL, *pVH, *pVL, *pPH;
    float* pS;
    cudaGetSymbolAddress((void**)&pXH, g_XH);   cudaGetSymbolAddress((void**)&pXL, g_XL);
    cudaGetSymbolAddress((void**)&pWTH, g_WTH); cudaGetSymbolAddress((void**)&pWTL, g_WTL);
    cudaGetSymbolAddress((void**)&pQH, g_QH);   cudaGetSymbolAddress((void**)&pQL, g_QL);
    cudaGetSymbolAddress((void**)&pKH, g_KH);   cudaGetSymbolAddress((void**)&pKL, g_KL);
    cudaGetSymbolAddress((void**)&pVH, g_VH);   cudaGetSymbolAddress((void**)&pVL, g_VL);
    cudaGetSymbolAddress((void**)&pPH, g_PH);
    cudaGetSymbolAddress((void**)&pS, g_S);

    dim3 tgrid(128, 128);
    dim3 ggrid(32, 32);

    // x -> hi/lo (already K-major for projections)
    split_kernel<<<NELEM / 1024, 256>>>((const float4*)x, pXH, pXL);

    // q = x @ Wq + bq   (B = Wq^T, K-major)
    transpose_split_kernel<<<tgrid, 256>>>(Wq, pWTH, pWTL);
    gemm128_kernel<3><<<ggrid, 256, GEMM_SMEM>>>(pXH, pXL, pWTH, pWTL, bq, 1.0f,
                                                 nullptr, pQH, pQL);
    // k = x @ Wk + bk
    transpose_split_kernel<<<tgrid, 256>>>(Wk, pWTH, pWTL);
    gemm128_kernel<3><<<ggrid, 256, GEMM_SMEM>>>(pXH, pXL, pWTH, pWTL, bk, 1.0f,
                                                 nullptr, pKH, pKL);
    // v = x @ Wv + bv   (row-major [t][d]; final GEMM contracts over columns)
    transpose_split_kernel<<<tgrid, 256>>>(Wv, pWTH, pWTL);
    gemm128_kernel<3><<<ggrid, 256, GEMM_SMEM>>>(pXH, pXL, pWTH, pWTL, bv, 1.0f,
                                                 nullptr, pVH, pVL);
    // scores = (q @ k^T) * 1/sqrt(d) -> fp32 g_S
    gemm128_kernel<3><<<ggrid, 256, GEMM_SMEM>>>(pQH, pQL, pKH, pKL, nullptr, ATT_SCALE,
                                                 pS, nullptr, nullptr);
    // P = softmax(scores, rows) -> fp16
    softmax_kernel<<<TDIM, 256>>>(pS, pPH);
    // out[i][j] = sum_m P[i][m] * v[j][m]   (plain fp16, 1 product)
    gemm128_kernel<1><<<ggrid, 256, GEMM_SMEM>>>(pPH, nullptr, pVH, nullptr, nullptr, 1.0f,
                                                 out, nullptr, nullptr);
}

// round 15
// speedup vs baseline: 1.2289x; 1.1543x over previous
#include <cuda_runtime.h>
#include <cuda_fp16.h>
#include <cstdint>

#define TDIM 4096
#define NELEM (TDIM * TDIM)
#define KITERS 64            // 4096 / 64
#define STAGE_BYTES 65536    // 4 operand tile slots x 128 rows x 128B
#define GEMM_SMEM (3 * STAGE_BYTES + 1024)
#define ATT_SCALE 0.015625f  // 1/sqrt(4096)

// ------------------------- scratch (__device__ globals) ---------------------
__device__ __half g_XH[NELEM],  g_XL[NELEM];
__device__ __half g_WTH[NELEM], g_WTL[NELEM];
__device__ __half g_QH[NELEM],  g_QL[NELEM];
__device__ __half g_KH[NELEM];
__device__ __half g_VH[NELEM];
__device__ __half g_PH[NELEM];
__device__ float g_S[NELEM];

// ------------------------------ helpers -------------------------------------
__device__ __forceinline__ uint32_t smem_to_u32(const void* p) {
    uint32_t a;
    asm("{ .reg .u64 t; cvta.to.shared.u64 t, %1; cvt.u32.u64 %0, t; }"
        : "=r"(a) : "l"(p));
    return a;
}
#define SMEM_SWIZZLE_128B(b) ((b) ^ (((b) >> 3) & 0x70))

__device__ __forceinline__ void ldsm4(uint32_t* r, uint32_t addr) {
    asm volatile("ldmatrix.sync.aligned.m8n8.x4.shared.b16 {%0,%1,%2,%3}, [%4];"
                 : "=r"(r[0]), "=r"(r[1]), "=r"(r[2]), "=r"(r[3]) : "r"(addr));
}
__device__ __forceinline__ void mma16816(float* c, const uint32_t* a, const uint32_t* b) {
    asm volatile("mma.sync.aligned.m16n8k16.row.col.f32.f16.f16.f32 "
                 "{%0,%1,%2,%3}, {%4,%5,%6,%7}, {%8,%9}, {%0,%1,%2,%3};"
                 : "+f"(c[0]), "+f"(c[1]), "+f"(c[2]), "+f"(c[3])
                 : "r"(a[0]), "r"(a[1]), "r"(a[2]), "r"(a[3]), "r"(b[0]), "r"(b[1]));
}

// --------------------------- fp32 -> fp16 hi/lo -----------------------------
__device__ __forceinline__ void split1(float v, unsigned short& h, unsigned short& l) {
    __half hb = __float2half_rn(v);
    __half lb = __float2half_rn(v - __half2float(hb));
    h = __half_as_ushort(hb);
    l = __half_as_ushort(lb);
}

// -------------------------- split (no transpose) ----------------------------
__global__ void __launch_bounds__(256)
split_kernel(const float4* __restrict__ in,
             __half* __restrict__ oh, __half* __restrict__ ol) {
    size_t i = (size_t)blockIdx.x * 256 + threadIdx.x;
    float4 v = in[i];
    unsigned short h0, h1, h2, h3, l0, l1, l2, l3;
    split1(v.x, h0, l0); split1(v.y, h1, l1); split1(v.z, h2, l2); split1(v.w, h3, l3);
    uint2 hp, lp;
    hp.x = (uint32_t)h0 | ((uint32_t)h1 << 16); hp.y = (uint32_t)h2 | ((uint32_t)h3 << 16);
    lp.x = (uint32_t)l0 | ((uint32_t)l1 << 16); lp.y = (uint32_t)l2 | ((uint32_t)l3 << 16);
    reinterpret_cast<uint2*>(oh)[i] = hp;
    reinterpret_cast<uint2*>(ol)[i] = lp;
}

// ---------------------------- transpose + split -----------------------------
__global__ void __launch_bounds__(256)
transpose_split_kernel(const float* __restrict__ in,
                       __half* __restrict__ oh, __half* __restrict__ ol) {
    __shared__ float t[32][33];
    int bx = blockIdx.x * 32, by = blockIdx.y * 32;
    int tx = threadIdx.x & 31, ty = threadIdx.x >> 5;
#pragma unroll
    for (int i = 0; i < 4; ++i)
        t[ty + 8 * i][tx] = in[(size_t)(by + ty + 8 * i) * TDIM + bx + tx];
    __syncthreads();
#pragma unroll
    for (int i = 0; i < 4; ++i) {
        float v = t[tx][ty + 8 * i];   // out[bx+ty+8i][by+tx] = in[by+tx][bx+ty+8i]
        unsigned short h, l;
        split1(v, h, l);
        size_t o = (size_t)(bx + ty + 8 * i) * TDIM + by + tx;
        oh[o] = __ushort_as_half(h);
        ol[o] = __ushort_as_half(l);
    }
}

// ------------------------- row softmax -> fp16 ------------------------------
__global__ void __launch_bounds__(256)
softmax_kernel(const float* __restrict__ S, __half* __restrict__ ph) {
    __shared__ float red[8];
    int tid = threadIdx.x, wid = tid >> 5, lid = tid & 31;
    const float4* src = reinterpret_cast<const float4*>(S + (size_t)blockIdx.x * TDIM);
    float4 v[4];
    float mx = -3.0e38f;
#pragma unroll
    for (int i = 0; i < 4; ++i) {
        v[i] = src[tid + i * 256];
        mx = fmaxf(mx, fmaxf(fmaxf(v[i].x, v[i].y), fmaxf(v[i].z, v[i].w)));
    }
#pragma unroll
    for (int o = 16; o; o >>= 1) mx = fmaxf(mx, __shfl_xor_sync(0xFFFFFFFFu, mx, o));
    if (lid == 0) red[wid] = mx;
    __syncthreads();
    mx = red[0];
#pragma unroll
    for (int i = 1; i < 8; ++i) mx = fmaxf(mx, red[i]);
    __syncthreads();
    float sum = 0.0f;
#pragma unroll
    for (int i = 0; i < 4; ++i) {
        v[i].x = __expf(v[i].x - mx); v[i].y = __expf(v[i].y - mx);
        v[i].z = __expf(v[i].z - mx); v[i].w = __expf(v[i].w - mx);
        sum += (v[i].x + v[i].y) + (v[i].z + v[i].w);
    }
#pragma unroll
    for (int o = 16; o; o >>= 1) sum += __shfl_xor_sync(0xFFFFFFFFu, sum, o);
    if (lid == 0) red[wid] = sum;
    __syncthreads();
    sum = red[0];
#pragma unroll
    for (int i = 1; i < 8; ++i) sum += red[i];
    float inv = __frcp_rn(sum);
    uint2* oph = reinterpret_cast<uint2*>(ph + (size_t)blockIdx.x * TDIM);
#pragma unroll
    for (int i = 0; i < 4; ++i) {
        __half h0 = __float2half_rn(v[i].x * inv), h1 = __float2half_rn(v[i].y * inv);
        __half h2 = __float2half_rn(v[i].z * inv), h3 = __float2half_rn(v[i].w * inv);
        uint2 hp;
        hp.x = (uint32_t)__half_as_ushort(h0) | ((uint32_t)__half_as_ushort(h1) << 16);
        hp.y = (uint32_t)__half_as_ushort(h2) | ((uint32_t)__half_as_ushort(h3) << 16);
        oph[tid + i * 256] = hp;
    }
}

// --------------------------- split-fp16 GEMM (mma.sync) ---------------------
// NPROD=3: D = Ah*Bh + Ah*Bl + Al*Bh   (err ~2^-22)
// NPROD=2: D = Ah*Bh + Al*Bh           (B fp16 only; err ~2^-12 RMS)
// NPROD=1: D = Ah*Bh                   (err ~2^-11)
// Operands K-major [4096][4096] fp16. CTA tile 128x128, K-chunk 64, 3 stages.
// Tile slots within a stage: Ah@0, Al@16K, Bh@32K, Bl@48K.
template <int NPROD>
__device__ __forceinline__ void load_quarter(
    uint32_t tb, int s,
    const __half* Ah, const __half* Al,
    const __half* Bh, const __half* Bl,
    int m0, int n0, int kit, int tid, int q) {
    int k0 = kit * 64;
    uint32_t sbase = tb + s * STAGE_BYTES;
    const int NOPS = (NPROD == 3) ? 4 : (NPROD == 2) ? 3 : 2;
#pragma unroll
    for (int j = 0; j < NOPS; ++j) {
        int i = q * NOPS + j;
        int cid = tid + i * 256;
        int opi = cid >> 10;                          // const per unrolled i
        int op = (NPROD == 1) ? (opi * 2) : opi;      // NPROD=1: {0,1}->{0,2}
        int rem = cid & 1023;
        int r = rem >> 3;
        int c = rem & 7;
        const __half* base = (op == 0) ? Ah : (op == 1) ? Al : (op == 2) ? Bh : Bl;
        int rb = (op < 2) ? m0 : n0;
        const char* src = (const char*)(base + (size_t)(rb + r) * TDIM + k0) + c * 16;
        uint32_t dst = sbase + op * 16384 + SMEM_SWIZZLE_128B((uint32_t)(r * 128 + c * 16));
        asm volatile("cp.async.cg.shared.global [%0], [%1], 16;" :: "r"(dst), "l"(src));
    }
}

template <int NPROD>
__global__ void __launch_bounds__(256, 1)
gemm128_kernel(const __half* __restrict__ Ah, const __half* __restrict__ Al,
               const __half* __restrict__ Bh, const __half* __restrict__ Bl,
               const float* __restrict__ bias, float scale,
               float* __restrict__ out_f,
               __half* __restrict__ oh, __half* __restrict__ ol) {
    extern __shared__ char smem[];
    uint32_t tb = (smem_to_u32(smem) + 1023u) & ~1023u;   // 1KB-aligned (SW128)
    int tid = threadIdx.x, lane = tid & 31, w = tid >> 5;
    int wm = w & 1, wn = w >> 1;                           // warp tile 64(m) x 32(n)
    int m0 = blockIdx.y * 128, n0 = blockIdx.x * 128;

    // per-lane ldmatrix address components (swizzle folds to constant XOR)
    int lr = lane & 7;
    int lxor = lr * 16;
    int a_row = wm * 64 + ((lane >> 3) & 1) * 8 + lr;      // +mi*16 later
    int a_kx  = ((lane >> 4) & 1) * 16;
    int b_row = wn * 32 + ((lane >> 4) & 1) * 8 + lr;      // +pair*16 later
    int b_kx  = ((lane >> 3) & 1) * 16;

    float acc[4][4][4];
#pragma unroll
    for (int mi = 0; mi < 4; ++mi)
#pragma unroll
        for (int ni = 0; ni < 4; ++ni)
#pragma unroll
            for (int c = 0; c < 4; ++c) acc[mi][ni][c] = 0.0f;

    // double-buffered fragments across ks-steps
    uint32_t aH[2][4][4], aL[2][4][4], bH[2][2][4], bL[2][2][4];

    // prologue: fill 2 of 3 stages
#pragma unroll
    for (int p = 0; p < 2; ++p) {
#pragma unroll
        for (int q = 0; q < 4; ++q)
            load_quarter<NPROD>(tb, p, Ah, Al, Bh, Bl, m0, n0, p, tid, q);
        asm volatile("cp.async.commit_group;" ::: "memory");
    }

    for (int it = 0; it < KITERS; ++it) {
        if (it == KITERS - 1) asm volatile("cp.async.wait_group 0;" ::: "memory");
        else                  asm volatile("cp.async.wait_group 1;" ::: "memory");
        // single barrier: proves every warp finished the previous chunk's reads
        // (so its buffer is refillable) and has completed its own wait_group.
        __syncthreads();
        uint32_t sbase = tb + (uint32_t)(it % 3) * STAGE_BYTES;
        bool pre = (it + 2 < KITERS);
        int ps = (it + 2) % 3;

        // fragment loader for one ks-step into buffer `buf`
        auto load_frags = [&](int ks, int buf) {
#pragma unroll
            for (int mi = 0; mi < 4; ++mi) {
                uint32_t off = (uint32_t)((a_row + mi * 16) * 128 + ((ks * 32 + a_kx) ^ lxor));
                ldsm4(aH[buf][mi], sbase + off);
                if (NPROD >= 2) ldsm4(aL[buf][mi], sbase + 16384u + off);
            }
#pragma unroll
            for (int p = 0; p < 2; ++p) {
                uint32_t off = (uint32_t)((b_row + p * 16) * 128 + ((ks * 32 + b_kx) ^ lxor));
                ldsm4(bH[buf][p], sbase + 32768u + off);
                if (NPROD == 3) ldsm4(bL[buf][p], sbase + 49152u + off);
            }
        };

        // fragments for ks=0 first, before any cp.async issue
        load_frags(0, 0);

#pragma unroll
        for (int ks = 0; ks < 4; ++ks) {
            int cur = ks & 1;
            // interleave 1/4 of next chunk's cp.async issue with this ks-step
            if (pre) load_quarter<NPROD>(tb, ps, Ah, Al, Bh, Bl, m0, n0, it + 2, tid, ks);
            // prefetch next ks-step's fragments before this step's MMAs
            if (ks < 3) load_frags(ks + 1, cur ^ 1);
#pragma unroll
            for (int mi = 0; mi < 4; ++mi)
#pragma unroll
                for (int ni = 0; ni < 4; ++ni) {
                    const uint32_t* fh = &bH[cur][ni >> 1][(ni & 1) * 2];
                    mma16816(acc[mi][ni], aH[cur][mi], fh);
                    if (NPROD == 3) {
                        const uint32_t* fl = &bL[cur][ni >> 1][(ni & 1) * 2];
                        mma16816(acc[mi][ni], aH[cur][mi], fl);
                    }
                    if (NPROD >= 2)
                        mma16816(acc[mi][ni], aL[cur][mi], fh);
                }
        }
        if (pre) asm volatile("cp.async.commit_group;" ::: "memory");
    }

    // epilogue: c0,c1 -> (row, col..col+1); c2,c3 -> (row+8, col..col+1)
    int er = lane >> 2, ec = (lane & 3) * 2;
    int m_base = m0 + wm * 64, n_base = n0 + wn * 32;
#pragma unroll
    for (int mi = 0; mi < 4; ++mi)
#pragma unroll
        for (int ni = 0; ni < 4; ++ni) {
            float* c = acc[mi][ni];
            int m = m_base + mi * 16 + er;
            int n = n_base + ni * 8 + ec;
            if (out_f != nullptr) {
                float2 v0 = { c[0] * scale, c[1] * scale };
                float2 v1 = { c[2] * scale, c[3] * scale };
                *reinterpret_cast<float2*>(out_f + (size_t)m * TDIM + n) = v0;
                *reinterpret_cast<float2*>(out_f + (size_t)(m + 8) * TDIM + n) = v1;
            } else {
                float b0 = bias[n], b1 = bias[n + 1];
                unsigned short h0, l0, h1, l1;
                split1(c[0] + b0, h0, l0);
                split1(c[1] + b1, h1, l1);
                *reinterpret_cast<uint32_t*>(oh + (size_t)m * TDIM + n) =
                    (uint32_t)h0 | ((uint32_t)h1 << 16);
                if (ol)
                    *reinterpret_cast<uint32_t*>(ol + (size_t)m * TDIM + n) =
                        (uint32_t)l0 | ((uint32_t)l1 << 16);
                split1(c[2] + b0, h0, l0);
                split1(c[3] + b1, h1, l1);
                *reinterpret_cast<uint32_t*>(oh + (size_t)(m + 8) * TDIM + n) =
                    (uint32_t)h0 | ((uint32_t)h1 << 16);
                if (ol)
                    *reinterpret_cast<uint32_t*>(ol + (size_t)(m + 8) * TDIM + n) =
                        (uint32_t)l0 | ((uint32_t)l1 << 16);
            }
        }
}

// -------------------------------- launcher ----------------------------------
extern "C" void kernel_launch(void* const* d_in, const int* in_sizes, int n_in,
                              void* d_out, int out_size) {
    (void)in_sizes; (void)n_in; (void)out_size;
    const float* x  = (const float*)d_in[0];
    const float* Wq = (const float*)d_in[1];
    const float* bq = (const float*)d_in[2];
    const float* Wk = (const float*)d_in[3];
    const float* bk = (const float*)d_in[4];
    const float* Wv = (const float*)d_in[5];
    const float* bv = (const float*)d_in[6];
    float* out = (float*)d_out;

    cudaFuncSetAttribute(gemm128_kernel<3>,
                         cudaFuncAttributeMaxDynamicSharedMemorySize, GEMM_SMEM);
    cudaFuncSetAttribute(gemm128_kernel<2>,
                         cudaFuncAttributeMaxDynamicSharedMemorySize, GEMM_SMEM);
    cudaFuncSetAttribute(gemm128_kernel<1>,
                         cudaFuncAttributeMaxDynamicSharedMemorySize, GEMM_SMEM);

    __half *pXH, *pXL, *pWTH, *pWTL, *pQH, *pQL, *pKH, *pVH, *pPH;
    float* pS;
    cudaGetSymbolAddress((void**)&pXH, g_XH);   cudaGetSymbolAddress((void**)&pXL, g_XL);
    cudaGetSymbolAddress((void**)&pWTH, g_WTH); cudaGetSymbolAddress((void**)&pWTL, g_WTL);
    cudaGetSymbolAddress((void**)&pQH, g_QH);   cudaGetSymbolAddress((void**)&pQL, g_QL);
    cudaGetSymbolAddress((void**)&pKH, g_KH);
    cudaGetSymbolAddress((void**)&pVH, g_VH);
    cudaGetSymbolAddress((void**)&pPH, g_PH);
    cudaGetSymbolAddress((void**)&pS, g_S);

    dim3 tgrid(128, 128);
    dim3 ggrid(32, 32);

    // x -> hi/lo (already K-major for projections)
    split_kernel<<<NELEM / 1024, 256>>>((const float4*)x, pXH, pXL);

    // q = x @ Wq + bq   (3-prod; store hi+lo — q feeds scores' exact side)
    transpose_split_kernel<<<tgrid, 256>>>(Wq, pWTH, pWTL);
    gemm128_kernel<3><<<ggrid, 256, GEMM_SMEM>>>(pXH, pXL, pWTH, pWTL, bq, 1.0f,
                                                 nullptr, pQH, pQL);
    // k = x @ Wk + bk   (3-prod; store hi only — scores uses fp16 k)
    transpose_split_kernel<<<tgrid, 256>>>(Wk, pWTH, pWTL);
    gemm128_kernel<3><<<ggrid, 256, GEMM_SMEM>>>(pXH, pXL, pWTH, pWTL, bk, 1.0f,
                                                 nullptr, pKH, nullptr);
    // v = x @ Wv + bv   (2-prod; store hi only — final GEMM uses fp16 v)
    transpose_split_kernel<<<tgrid, 256>>>(Wv, pWTH, pWTL);
    gemm128_kernel<2><<<ggrid, 256, GEMM_SMEM>>>(pXH, pXL, pWTH, nullptr, bv, 1.0f,
                                                 nullptr, pVH, nullptr);
    // scores = (q @ k^T) * 1/sqrt(d)  (2-prod: Qh*Kh + Ql*Kh) -> fp32 g_S
    gemm128_kernel<2><<<ggrid, 256, GEMM_SMEM>>>(pQH, pQL, pKH, nullptr, nullptr, ATT_SCALE,
                                                 pS, nullptr, nullptr);
    // P = softmax(scores, rows) -> fp16
    softmax_kernel<<<TDIM, 256>>>(pS, pPH);
    // out[i][j] = sum_m P[i][m] * v[j][m]   (plain fp16, 1 product)
    gemm128_kernel<1><<<ggrid, 256, GEMM_SMEM>>>(pPH, nullptr, pVH, nullptr, nullptr, 1.0f,
                                                 out, nullptr, nullptr);
}

// round 16
// speedup vs baseline: 1.5634x; 1.2722x over previous
#include <cuda_runtime.h>
#include <cuda_fp16.h>
#include <cstdint>

#define TDIM 4096
#define NELEM (TDIM * TDIM)
#define KITERS 64            // 4096 / 64
#define STAGE_BYTES 65536    // 4 operand tile slots x 128 rows x 128B
#define GEMM_SMEM (3 * STAGE_BYTES + 1024)
#define ATT_SCALE 0.015625f  // 1/sqrt(4096)

// ------------------------- scratch (__device__ globals) ---------------------
__device__ __half g_XH[NELEM],  g_XL[NELEM];
__device__ __half g_WTH[NELEM], g_WTL[NELEM];
__device__ __half g_QH[NELEM];
__device__ __half g_KH[NELEM];
__device__ __half g_VH[NELEM];
__device__ __half g_PH[NELEM];
__device__ float g_S[NELEM];

// ------------------------------ helpers -------------------------------------
__device__ __forceinline__ uint32_t smem_to_u32(const void* p) {
    uint32_t a;
    asm("{ .reg .u64 t; cvta.to.shared.u64 t, %1; cvt.u32.u64 %0, t; }"
        : "=r"(a) : "l"(p));
    return a;
}
#define SMEM_SWIZZLE_128B(b) ((b) ^ (((b) >> 3) & 0x70))

__device__ __forceinline__ void ldsm4(uint32_t* r, uint32_t addr) {
    asm volatile("ldmatrix.sync.aligned.m8n8.x4.shared.b16 {%0,%1,%2,%3}, [%4];"
                 : "=r"(r[0]), "=r"(r[1]), "=r"(r[2]), "=r"(r[3]) : "r"(addr));
}
__device__ __forceinline__ void mma16816(float* c, const uint32_t* a, const uint32_t* b) {
    asm volatile("mma.sync.aligned.m16n8k16.row.col.f32.f16.f16.f32 "
                 "{%0,%1,%2,%3}, {%4,%5,%6,%7}, {%8,%9}, {%0,%1,%2,%3};"
                 : "+f"(c[0]), "+f"(c[1]), "+f"(c[2]), "+f"(c[3])
                 : "r"(a[0]), "r"(a[1]), "r"(a[2]), "r"(a[3]), "r"(b[0]), "r"(b[1]));
}

// --------------------------- fp32 -> fp16 hi/lo -----------------------------
__device__ __forceinline__ void split1(float v, unsigned short& h, unsigned short& l) {
    __half hb = __float2half_rn(v);
    __half lb = __float2half_rn(v - __half2float(hb));
    h = __half_as_ushort(hb);
    l = __half_as_ushort(lb);
}

// -------------------------- split (no transpose) ----------------------------
__global__ void __launch_bounds__(256)
split_kernel(const float4* __restrict__ in,
             __half* __restrict__ oh, __half* __restrict__ ol) {
    size_t i = (size_t)blockIdx.x * 256 + threadIdx.x;
    float4 v = in[i];
    unsigned short h0, h1, h2, h3, l0, l1, l2, l3;
    split1(v.x, h0, l0); split1(v.y, h1, l1); split1(v.z, h2, l2); split1(v.w, h3, l3);
    uint2 hp, lp;
    hp.x = (uint32_t)h0 | ((uint32_t)h1 << 16); hp.y = (uint32_t)h2 | ((uint32_t)h3 << 16);
    lp.x = (uint32_t)l0 | ((uint32_t)l1 << 16); lp.y = (uint32_t)l2 | ((uint32_t)l3 << 16);
    reinterpret_cast<uint2*>(oh)[i] = hp;
    reinterpret_cast<uint2*>(ol)[i] = lp;
}

// ---------------------------- transpose + split -----------------------------
__global__ void __launch_bounds__(256)
transpose_split_kernel(const float* __restrict__ in,
                       __half* __restrict__ oh, __half* __restrict__ ol) {
    __shared__ float t[32][33];
    int bx = blockIdx.x * 32, by = blockIdx.y * 32;
    int tx = threadIdx.x & 31, ty = threadIdx.x >> 5;
#pragma unroll
    for (int i = 0; i < 4; ++i)
        t[ty + 8 * i][tx] = in[(size_t)(by + ty + 8 * i) * TDIM + bx + tx];
    __syncthreads();
#pragma unroll
    for (int i = 0; i < 4; ++i) {
        float v = t[tx][ty + 8 * i];   // out[bx+ty+8i][by+tx] = in[by+tx][bx+ty+8i]
        unsigned short h, l;
        split1(v, h, l);
        size_t o = (size_t)(bx + ty + 8 * i) * TDIM + by + tx;
        oh[o] = __ushort_as_half(h);
        ol[o] = __ushort_as_half(l);
    }
}

// ------------------------- row softmax -> fp16 ------------------------------
__global__ void __launch_bounds__(256)
softmax_kernel(const float* __restrict__ S, __half* __restrict__ ph) {
    __shared__ float red[8];
    int tid = threadIdx.x, wid = tid >> 5, lid = tid & 31;
    const float4* src = reinterpret_cast<const float4*>(S + (size_t)blockIdx.x * TDIM);
    float4 v[4];
    float mx = -3.0e38f;
#pragma unroll
    for (int i = 0; i < 4; ++i) {
        v[i] = src[tid + i * 256];
        mx = fmaxf(mx, fmaxf(fmaxf(v[i].x, v[i].y), fmaxf(v[i].z, v[i].w)));
    }
#pragma unroll
    for (int o = 16; o; o >>= 1) mx = fmaxf(mx, __shfl_xor_sync(0xFFFFFFFFu, mx, o));
    if (lid == 0) red[wid] = mx;
    __syncthreads();
    mx = red[0];
#pragma unroll
    for (int i = 1; i < 8; ++i) mx = fmaxf(mx, red[i]);
    __syncthreads();
    float sum = 0.0f;
#pragma unroll
    for (int i = 0; i < 4; ++i) {
        v[i].x = __expf(v[i].x - mx); v[i].y = __expf(v[i].y - mx);
        v[i].z = __expf(v[i].z - mx); v[i].w = __expf(v[i].w - mx);
        sum += (v[i].x + v[i].y) + (v[i].z + v[i].w);
    }
#pragma unroll
    for (int o = 16; o; o >>= 1) sum += __shfl_xor_sync(0xFFFFFFFFu, sum, o);
    if (lid == 0) red[wid] = sum;
    __syncthreads();
    sum = red[0];
#pragma unroll
    for (int i = 1; i < 8; ++i) sum += red[i];
    float inv = __frcp_rn(sum);
    uint2* oph = reinterpret_cast<uint2*>(ph + (size_t)blockIdx.x * TDIM);
#pragma unroll
    for (int i = 0; i < 4; ++i) {
        __half h0 = __float2half_rn(v[i].x * inv), h1 = __float2half_rn(v[i].y * inv);
        __half h2 = __float2half_rn(v[i].z * inv), h3 = __float2half_rn(v[i].w * inv);
        uint2 hp;
        hp.x = (uint32_t)__half_as_ushort(h0) | ((uint32_t)__half_as_ushort(h1) << 16);
        hp.y = (uint32_t)__half_as_ushort(h2) | ((uint32_t)__half_as_ushort(h3) << 16);
        oph[tid + i * 256] = hp;
    }
}

// --------------------------- split-fp16 GEMM (mma.sync) ---------------------
// NPROD=3: D = Ah*Bh + Ah*Bl + Al*Bh   (err ~2^-22)
// NPROD=2: D = Ah*Bh + Al*Bh           (B fp16 only; err ~2^-12 RMS)
// NPROD=1: D = Ah*Bh                   (err ~2^-11)
// Operands K-major [4096][4096] fp16. CTA tile 128x128, K-chunk 64, 3 stages.
// Tile slots within a stage: Ah@0, Al@16K, Bh@32K, Bl@48K.
template <int NPROD>
__device__ __forceinline__ void load_quarter(
    uint32_t tb, int s,
    const __half* Ah, const __half* Al,
    const __half* Bh, const __half* Bl,
    int m0, int n0, int kit, int tid, int q) {
    int k0 = kit * 64;
    uint32_t sbase = tb + s * STAGE_BYTES;
    const int NOPS = (NPROD == 3) ? 4 : (NPROD == 2) ? 3 : 2;
#pragma unroll
    for (int j = 0; j < NOPS; ++j) {
        int i = q * NOPS + j;
        int cid = tid + i * 256;
        int opi = cid >> 10;                          // const per unrolled i
        int op = (NPROD == 1) ? (opi * 2) : opi;      // NPROD=1: {0,1}->{0,2}
        int rem = cid & 1023;
        int r = rem >> 3;
        int c = rem & 7;
        const __half* base = (op == 0) ? Ah : (op == 1) ? Al : (op == 2) ? Bh : Bl;
        int rb = (op < 2) ? m0 : n0;
        const char* src = (const char*)(base + (size_t)(rb + r) * TDIM + k0) + c * 16;
        uint32_t dst = sbase + op * 16384 + SMEM_SWIZZLE_128B((uint32_t)(r * 128 + c * 16));
        asm volatile("cp.async.cg.shared.global [%0], [%1], 16;" :: "r"(dst), "l"(src));
    }
}

template <int NPROD>
__global__ void __launch_bounds__(256, 1)
gemm128_kernel(const __half* __restrict__ Ah, const __half* __restrict__ Al,
               const __half* __restrict__ Bh, const __half* __restrict__ Bl,
               const float* __restrict__ bias, float scale,
               float* __restrict__ out_f,
               __half* __restrict__ oh, __half* __restrict__ ol) {
    extern __shared__ char smem[];
    uint32_t tb = (smem_to_u32(smem) + 1023u) & ~1023u;   // 1KB-aligned (SW128)
    int tid = threadIdx.x, lane = tid & 31, w = tid >> 5;
    int wm = w & 1, wn = w >> 1;                           // warp tile 64(m) x 32(n)
    int m0 = blockIdx.y * 128, n0 = blockIdx.x * 128;

    // per-lane ldmatrix address components (swizzle folds to constant XOR)
    int lr = lane & 7;
    int lxor = lr * 16;
    int a_row = wm * 64 + ((lane >> 3) & 1) * 8 + lr;      // +mi*16 later
    int a_kx  = ((lane >> 4) & 1) * 16;
    int b_row = wn * 32 + ((lane >> 4) & 1) * 8 + lr;      // +pair*16 later
    int b_kx  = ((lane >> 3) & 1) * 16;

    float acc[4][4][4];
#pragma unroll
    for (int mi = 0; mi < 4; ++mi)
#pragma unroll
        for (int ni = 0; ni < 4; ++ni)
#pragma unroll
            for (int c = 0; c < 4; ++c) acc[mi][ni][c] = 0.0f;

    // double-buffered fragments across ks-steps
    uint32_t aH[2][4][4], aL[2][4][4], bH[2][2][4], bL[2][2][4];

    // prologue: fill 2 of 3 stages
#pragma unroll
    for (int p = 0; p < 2; ++p) {
#pragma unroll
        for (int q = 0; q < 4; ++q)
            load_quarter<NPROD>(tb, p, Ah, Al, Bh, Bl, m0, n0, p, tid, q);
        asm volatile("cp.async.commit_group;" ::: "memory");
    }

    for (int it = 0; it < KITERS; ++it) {
        if (it == KITERS - 1) asm volatile("cp.async.wait_group 0;" ::: "memory");
        else                  asm volatile("cp.async.wait_group 1;" ::: "memory");
        // single barrier: proves every warp finished the previous chunk's reads
        // (so its buffer is refillable) and has completed its own wait_group.
        __syncthreads();
        uint32_t sbase = tb + (uint32_t)(it % 3) * STAGE_BYTES;
        bool pre = (it + 2 < KITERS);
        int ps = (it + 2) % 3;

        // fragment loader for one ks-step into buffer `buf`
        auto load_frags = [&](int ks, int buf) {
#pragma unroll
            for (int mi = 0; mi < 4; ++mi) {
                uint32_t off = (uint32_t)((a_row + mi * 16) * 128 + ((ks * 32 + a_kx) ^ lxor));
                ldsm4(aH[buf][mi], sbase + off);
                if (NPROD >= 2) ldsm4(aL[buf][mi], sbase + 16384u + off);
            }
#pragma unroll
            for (int p = 0; p < 2; ++p) {
                uint32_t off = (uint32_t)((b_row + p * 16) * 128 + ((ks * 32 + b_kx) ^ lxor));
                ldsm4(bH[buf][p], sbase + 32768u + off);
                if (NPROD == 3) ldsm4(bL[buf][p], sbase + 49152u + off);
            }
        };

        // fragments for ks=0 first, before any cp.async issue
        load_frags(0, 0);

#pragma unroll
        for (int ks = 0; ks < 4; ++ks) {
            int cur = ks & 1;
            // interleave 1/4 of next chunk's cp.async issue with this ks-step
            if (pre) load_quarter<NPROD>(tb, ps, Ah, Al, Bh, Bl, m0, n0, it + 2, tid, ks);
            // prefetch next ks-step's fragments before this step's MMAs
            if (ks < 3) load_frags(ks + 1, cur ^ 1);
#pragma unroll
            for (int mi = 0; mi < 4; ++mi)
#pragma unroll
                for (int ni = 0; ni < 4; ++ni) {
                    const uint32_t* fh = &bH[cur][ni >> 1][(ni & 1) * 2];
                    mma16816(acc[mi][ni], aH[cur][mi], fh);
                    if (NPROD == 3) {
                        const uint32_t* fl = &bL[cur][ni >> 1][(ni & 1) * 2];
                        mma16816(acc[mi][ni], aH[cur][mi], fl);
                    }
                    if (NPROD >= 2)
                        mma16816(acc[mi][ni], aL[cur][mi], fh);
                }
        }
        if (pre) asm volatile("cp.async.commit_group;" ::: "memory");
    }

    // epilogue: c0,c1 -> (row, col..col+1); c2,c3 -> (row+8, col..col+1)
    int er = lane >> 2, ec = (lane & 3) * 2;
    int m_base = m0 + wm * 64, n_base = n0 + wn * 32;
#pragma unroll
    for (int mi = 0; mi < 4; ++mi)
#pragma unroll
        for (int ni = 0; ni < 4; ++ni) {
            float* c = acc[mi][ni];
            int m = m_base + mi * 16 + er;
            int n = n_base + ni * 8 + ec;
            if (out_f != nullptr) {
                float2 v0 = { c[0] * scale, c[1] * scale };
                float2 v1 = { c[2] * scale, c[3] * scale };
                *reinterpret_cast<float2*>(out_f + (size_t)m * TDIM + n) = v0;
                *reinterpret_cast<float2*>(out_f + (size_t)(m + 8) * TDIM + n) = v1;
            } else {
                float b0 = bias[n], b1 = bias[n + 1];
                unsigned short h0, l0, h1, l1;
                split1(c[0] + b0, h0, l0);
                split1(c[1] + b1, h1, l1);
                *reinterpret_cast<uint32_t*>(oh + (size_t)m * TDIM + n) =
                    (uint32_t)h0 | ((uint32_t)h1 << 16);
                if (ol)
                    *reinterpret_cast<uint32_t*>(ol + (size_t)m * TDIM + n) =
                        (uint32_t)l0 | ((uint32_t)l1 << 16);
                split1(c[2] + b0, h0, l0);
                split1(c[3] + b1, h1, l1);
                *reinterpret_cast<uint32_t*>(oh + (size_t)(m + 8) * TDIM + n) =
                    (uint32_t)h0 | ((uint32_t)h1 << 16);
                if (ol)
                    *reinterpret_cast<uint32_t*>(ol + (size_t)(m + 8) * TDIM + n) =
                        (uint32_t)l0 | ((uint32_t)l1 << 16);
            }
        }
}

// -------------------------------- launcher ----------------------------------
extern "C" void kernel_launch(void* const* d_in, const int* in_sizes, int n_in,
                              void* d_out, int out_size) {
    (void)in_sizes; (void)n_in; (void)out_size;
    const float* x  = (const float*)d_in[0];
    const float* Wq = (const float*)d_in[1];
    const float* bq = (const float*)d_in[2];
    const float* Wk = (const float*)d_in[3];
    const float* bk = (const float*)d_in[4];
    const float* Wv = (const float*)d_in[5];
    const float* bv = (const float*)d_in[6];
    float* out = (float*)d_out;

    cudaFuncSetAttribute(gemm128_kernel<2>,
                         cudaFuncAttributeMaxDynamicSharedMemorySize, GEMM_SMEM);
    cudaFuncSetAttribute(gemm128_kernel<1>,
                         cudaFuncAttributeMaxDynamicSharedMemorySize, GEMM_SMEM);

    __half *pXH, *pXL, *pWTH, *pWTL, *pQH, *pKH, *pVH, *pPH;
    float* pS;
    cudaGetSymbolAddress((void**)&pXH, g_XH);   cudaGetSymbolAddress((void**)&pXL, g_XL);
    cudaGetSymbolAddress((void**)&pWTH, g_WTH); cudaGetSymbolAddress((void**)&pWTL, g_WTL);
    cudaGetSymbolAddress((void**)&pQH, g_QH);
    cudaGetSymbolAddress((void**)&pKH, g_KH);
    cudaGetSymbolAddress((void**)&pVH, g_VH);
    cudaGetSymbolAddress((void**)&pPH, g_PH);
    cudaGetSymbolAddress((void**)&pS, g_S);

    dim3 tgrid(128, 128);
    dim3 ggrid(32, 32);

    // x -> hi/lo (already K-major for projections)
    split_kernel<<<NELEM / 1024, 256>>>((const float4*)x, pXH, pXL);

    // q = x @ Wq + bq   (2-prod; store hi only — scores consumes fp16 q)
    transpose_split_kernel<<<tgrid, 256>>>(Wq, pWTH, pWTL);
    gemm128_kernel<2><<<ggrid, 256, GEMM_SMEM>>>(pXH, pXL, pWTH, nullptr, bq, 1.0f,
                                                 nullptr, pQH, nullptr);
    // k = x @ Wk + bk   (2-prod; store hi only)
    transpose_split_kernel<<<tgrid, 256>>>(Wk, pWTH, pWTL);
    gemm128_kernel<2><<<ggrid, 256, GEMM_SMEM>>>(pXH, pXL, pWTH, nullptr, bk, 1.0f,
                                                 nullptr, pKH, nullptr);
    // v = x @ Wv + bv   (2-prod; store hi only)
    transpose_split_kernel<<<tgrid, 256>>>(Wv, pWTH, pWTL);
    gemm128_kernel<2><<<ggrid, 256, GEMM_SMEM>>>(pXH, pXL, pWTH, nullptr, bv, 1.0f,
                                                 nullptr, pVH, nullptr);
    // scores = (q @ k^T) * 1/sqrt(d)  (1-prod: Qh*Kh) -> fp32 g_S
    gemm128_kernel<1><<<ggrid, 256, GEMM_SMEM>>>(pQH, nullptr, pKH, nullptr, nullptr, ATT_SCALE,
                                                 pS, nullptr, nullptr);
    // P = softmax(scores, rows) -> fp16
    softmax_kernel<<<TDIM, 256>>>(pS, pPH);
    // out[i][j] = sum_m P[i][m] * v[j][m]   (plain fp16, 1 product)
    gemm128_kernel<1><<<ggrid, 256, GEMM_SMEM>>>(pPH, nullptr, pVH, nullptr, nullptr, 1.0f,
                                                 out, nullptr, nullptr);
}

// round 17
// speedup vs baseline: 2.1133x; 1.3517x over previous
#include <cuda_runtime.h>
#include <cuda_fp16.h>
#include <cstdint>

#define TDIM 4096
#define NELEM (TDIM * TDIM)
#define KITERS 64            // 4096 / 64
#define STAGE_BYTES 65536    // 4 operand tile slots x 128 rows x 128B
#define GEMM_SMEM (3 * STAGE_BYTES + 1024)
#define ATT_SCALE 0.015625f  // 1/sqrt(4096)

// ------------------------- scratch (__device__ globals) ---------------------
__device__ __half g_XH[NELEM];
__device__ __half g_WTH[NELEM];
__device__ __half g_QH[NELEM];
__device__ __half g_KH[NELEM];
__device__ __half g_VH[NELEM];
__device__ __half g_PH[NELEM];
__device__ float g_S[NELEM];

// ------------------------------ helpers -------------------------------------
__device__ __forceinline__ uint32_t smem_to_u32(const void* p) {
    uint32_t a;
    asm("{ .reg .u64 t; cvta.to.shared.u64 t, %1; cvt.u32.u64 %0, t; }"
        : "=r"(a) : "l"(p));
    return a;
}
#define SMEM_SWIZZLE_128B(b) ((b) ^ (((b) >> 3) & 0x70))

__device__ __forceinline__ void ldsm4(uint32_t* r, uint32_t addr) {
    asm volatile("ldmatrix.sync.aligned.m8n8.x4.shared.b16 {%0,%1,%2,%3}, [%4];"
                 : "=r"(r[0]), "=r"(r[1]), "=r"(r[2]), "=r"(r[3]) : "r"(addr));
}
__device__ __forceinline__ void mma16816(float* c, const uint32_t* a, const uint32_t* b) {
    asm volatile("mma.sync.aligned.m16n8k16.row.col.f32.f16.f16.f32 "
                 "{%0,%1,%2,%3}, {%4,%5,%6,%7}, {%8,%9}, {%0,%1,%2,%3};"
                 : "+f"(c[0]), "+f"(c[1]), "+f"(c[2]), "+f"(c[3])
                 : "r"(a[0]), "r"(a[1]), "r"(a[2]), "r"(a[3]), "r"(b[0]), "r"(b[1]));
}

// --------------------------- fp32 -> fp16 hi/lo -----------------------------
__device__ __forceinline__ void split1(float v, unsigned short& h, unsigned short& l) {
    __half hb = __float2half_rn(v);
    __half lb = __float2half_rn(v - __half2float(hb));
    h = __half_as_ushort(hb);
    l = __half_as_ushort(lb);
}

// -------------------------- fp32 -> fp16 convert ----------------------------
__global__ void __launch_bounds__(256)
cvt_kernel(const float4* __restrict__ in, __half* __restrict__ oh) {
    size_t i = (size_t)blockIdx.x * 256 + threadIdx.x;
    float4 v = in[i];
    __half h0 = __float2half_rn(v.x), h1 = __float2half_rn(v.y);
    __half h2 = __float2half_rn(v.z), h3 = __float2half_rn(v.w);
    uint2 hp;
    hp.x = (uint32_t)__half_as_ushort(h0) | ((uint32_t)__half_as_ushort(h1) << 16);
    hp.y = (uint32_t)__half_as_ushort(h2) | ((uint32_t)__half_as_ushort(h3) << 16);
    reinterpret_cast<uint2*>(oh)[i] = hp;
}

// --------------------------- transpose -> fp16 ------------------------------
__global__ void __launch_bounds__(256)
transpose_half_kernel(const float* __restrict__ in, __half* __restrict__ oh) {
    __shared__ float t[32][33];
    int bx = blockIdx.x * 32, by = blockIdx.y * 32;
    int tx = threadIdx.x & 31, ty = threadIdx.x >> 5;
#pragma unroll
    for (int i = 0; i < 4; ++i)
        t[ty + 8 * i][tx] = in[(size_t)(by + ty + 8 * i) * TDIM + bx + tx];
    __syncthreads();
#pragma unroll
    for (int i = 0; i < 4; ++i) {
        float v = t[tx][ty + 8 * i];   // out[bx+ty+8i][by+tx] = in[by+tx][bx+ty+8i]
        size_t o = (size_t)(bx + ty + 8 * i) * TDIM + by + tx;
        oh[o] = __float2half_rn(v);
    }
}

// ------------------------- row softmax -> fp16 ------------------------------
__global__ void __launch_bounds__(256)
softmax_kernel(const float* __restrict__ S, __half* __restrict__ ph) {
    __shared__ float red[8];
    int tid = threadIdx.x, wid = tid >> 5, lid = tid & 31;
    const float4* src = reinterpret_cast<const float4*>(S + (size_t)blockIdx.x * TDIM);
    float4 v[4];
    float mx = -3.0e38f;
#pragma unroll
    for (int i = 0; i < 4; ++i) {
        v[i] = src[tid + i * 256];
        mx = fmaxf(mx, fmaxf(fmaxf(v[i].x, v[i].y), fmaxf(v[i].z, v[i].w)));
    }
#pragma unroll
    for (int o = 16; o; o >>= 1) mx = fmaxf(mx, __shfl_xor_sync(0xFFFFFFFFu, mx, o));
    if (lid == 0) red[wid] = mx;
    __syncthreads();
    mx = red[0];
#pragma unroll
    for (int i = 1; i < 8; ++i) mx = fmaxf(mx, red[i]);
    __syncthreads();
    float sum = 0.0f;
#pragma unroll
    for (int i = 0; i < 4; ++i) {
        v[i].x = __expf(v[i].x - mx); v[i].y = __expf(v[i].y - mx);
        v[i].z = __expf(v[i].z - mx); v[i].w = __expf(v[i].w - mx);
        sum += (v[i].x + v[i].y) + (v[i].z + v[i].w);
    }
#pragma unroll
    for (int o = 16; o; o >>= 1) sum += __shfl_xor_sync(0xFFFFFFFFu, sum, o);
    if (lid == 0) red[wid] = sum;
    __syncthreads();
    sum = red[0];
#pragma unroll
    for (int i = 1; i < 8; ++i) sum += red[i];
    float inv = __frcp_rn(sum);
    uint2* oph = reinterpret_cast<uint2*>(ph + (size_t)blockIdx.x * TDIM);
#pragma unroll
    for (int i = 0; i < 4; ++i) {
        __half h0 = __float2half_rn(v[i].x * inv), h1 = __float2half_rn(v[i].y * inv);
        __half h2 = __float2half_rn(v[i].z * inv), h3 = __float2half_rn(v[i].w * inv);
        uint2 hp;
        hp.x = (uint32_t)__half_as_ushort(h0) | ((uint32_t)__half_as_ushort(h1) << 16);
        hp.y = (uint32_t)__half_as_ushort(h2) | ((uint32_t)__half_as_ushort(h3) << 16);
        oph[tid + i * 256] = hp;
    }
}

// --------------------------- fp16 GEMM (mma.sync) ---------------------------
// NPROD=1: D = Ah*Bh (plain fp16, fp32 accum).
// Operands K-major [4096][4096] fp16. CTA tile 128x128, K-chunk 64, 3 stages.
// Tile slots within a stage: Ah@0, (unused)@16K, Bh@32K, (unused)@48K.
template <int NPROD>
__device__ __forceinline__ void load_quarter(
    uint32_t tb, int s,
    const __half* Ah, const __half* Bh,
    int m0, int n0, int kit, int tid, int q) {
    int k0 = kit * 64;
    uint32_t sbase = tb + s * STAGE_BYTES;
    const int NOPS = 2;
#pragma unroll
    for (int j = 0; j < NOPS; ++j) {
        int i = q * NOPS + j;
        int cid = tid + i * 256;
        int opi = cid >> 10;                          // const per unrolled i
        int op = opi * 2;                             // {0,1}->{0,2}
        int rem = cid & 1023;
        int r = rem >> 3;
        int c = rem & 7;
        const __half* base = (op == 0) ? Ah : Bh;
        int rb = (op == 0) ? m0 : n0;
        const char* src = (const char*)(base + (size_t)(rb + r) * TDIM + k0) + c * 16;
        uint32_t dst = sbase + op * 16384 + SMEM_SWIZZLE_128B((uint32_t)(r * 128 + c * 16));
        asm volatile("cp.async.cg.shared.global [%0], [%1], 16;" :: "r"(dst), "l"(src));
    }
}

template <int NPROD>
__global__ void __launch_bounds__(256, 1)
gemm128_kernel(const __half* __restrict__ Ah, const __half* __restrict__ Bh,
               const float* __restrict__ bias, float scale,
               float* __restrict__ out_f, __half* __restrict__ oh) {
    extern __shared__ char smem[];
    uint32_t tb = (smem_to_u32(smem) + 1023u) & ~1023u;   // 1KB-aligned (SW128)
    int tid = threadIdx.x, lane = tid & 31, w = tid >> 5;
    int wm = w & 1, wn = w >> 1;                           // warp tile 64(m) x 32(n)
    int m0 = blockIdx.y * 128, n0 = blockIdx.x * 128;

    // per-lane ldmatrix address components (swizzle folds to constant XOR)
    int lr = lane & 7;
    int lxor = lr * 16;
    int a_row = wm * 64 + ((lane >> 3) & 1) * 8 + lr;      // +mi*16 later
    int a_kx  = ((lane >> 4) & 1) * 16;
    int b_row = wn * 32 + ((lane >> 4) & 1) * 8 + lr;      // +pair*16 later
    int b_kx  = ((lane >> 3) & 1) * 16;

    float acc[4][4][4];
#pragma unroll
    for (int mi = 0; mi < 4; ++mi)
#pragma unroll
        for (int ni = 0; ni < 4; ++ni)
#pragma unroll
            for (int c = 0; c < 4; ++c) acc[mi][ni][c] = 0.0f;

    // double-buffered fragments across ks-steps
    uint32_t aH[2][4][4], bH[2][2][4];

    // prologue: fill 2 of 3 stages
#pragma unroll
    for (int p = 0; p < 2; ++p) {
#pragma unroll
        for (int q = 0; q < 4; ++q)
            load_quarter<NPROD>(tb, p, Ah, Bh, m0, n0, p, tid, q);
        asm volatile("cp.async.commit_group;" ::: "memory");
    }

    for (int it = 0; it < KITERS; ++it) {
        if (it == KITERS - 1) asm volatile("cp.async.wait_group 0;" ::: "memory");
        else                  asm volatile("cp.async.wait_group 1;" ::: "memory");
        // single barrier: proves every warp finished the previous chunk's reads
        // (so its buffer is refillable) and has completed its own wait_group.
        __syncthreads();
        uint32_t sbase = tb + (uint32_t)(it % 3) * STAGE_BYTES;
        bool pre = (it + 2 < KITERS);
        int ps = (it + 2) % 3;

        // fragment loader for one ks-step into buffer `buf`
        auto load_frags = [&](int ks, int buf) {
#pragma unroll
            for (int mi = 0; mi < 4; ++mi) {
                uint32_t off = (uint32_t)((a_row + mi * 16) * 128 + ((ks * 32 + a_kx) ^ lxor));
                ldsm4(aH[buf][mi], sbase + off);
            }
#pragma unroll
            for (int p = 0; p < 2; ++p) {
                uint32_t off = (uint32_t)((b_row + p * 16) * 128 + ((ks * 32 + b_kx) ^ lxor));
                ldsm4(bH[buf][p], sbase + 32768u + off);
            }
        };

        // fragments for ks=0 first, before any cp.async issue
        load_frags(0, 0);

#pragma unroll
        for (int ks = 0; ks < 4; ++ks) {
            int cur = ks & 1;
            // interleave 1/4 of next chunk's cp.async issue with this ks-step
            if (pre) load_quarter<NPROD>(tb, ps, Ah, Bh, m0, n0, it + 2, tid, ks);
            // prefetch next ks-step's fragments before this step's MMAs
            if (ks < 3) load_frags(ks + 1, cur ^ 1);
#pragma unroll
            for (int mi = 0; mi < 4; ++mi)
#pragma unroll
                for (int ni = 0; ni < 4; ++ni) {
                    const uint32_t* fh = &bH[cur][ni >> 1][(ni & 1) * 2];
                    mma16816(acc[mi][ni], aH[cur][mi], fh);
                }
        }
        if (pre) asm volatile("cp.async.commit_group;" ::: "memory");
    }

    // epilogue: c0,c1 -> (row, col..col+1); c2,c3 -> (row+8, col..col+1)
    int er = lane >> 2, ec = (lane & 3) * 2;
    int m_base = m0 + wm * 64, n_base = n0 + wn * 32;
#pragma unroll
    for (int mi = 0; mi < 4; ++mi)
#pragma unroll
        for (int ni = 0; ni < 4; ++ni) {
            float* c = acc[mi][ni];
            int m = m_base + mi * 16 + er;
            int n = n_base + ni * 8 + ec;
            if (out_f != nullptr) {
                float2 v0 = { c[0] * scale, c[1] * scale };
                float2 v1 = { c[2] * scale, c[3] * scale };
                *reinterpret_cast<float2*>(out_f + (size_t)m * TDIM + n) = v0;
                *reinterpret_cast<float2*>(out_f + (size_t)(m + 8) * TDIM + n) = v1;
            } else {
                float b0 = bias[n], b1 = bias[n + 1];
                __half h0 = __float2half_rn(c[0] + b0);
                __half h1 = __float2half_rn(c[1] + b1);
                *reinterpret_cast<uint32_t*>(oh + (size_t)m * TDIM + n) =
                    (uint32_t)__half_as_ushort(h0) | ((uint32_t)__half_as_ushort(h1) << 16);
                __half h2 = __float2half_rn(c[2] + b0);
                __half h3 = __float2half_rn(c[3] + b1);
                *reinterpret_cast<uint32_t*>(oh + (size_t)(m + 8) * TDIM + n) =
                    (uint32_t)__half_as_ushort(h2) | ((uint32_t)__half_as_ushort(h3) << 16);
            }
        }
}

// -------------------------------- launcher ----------------------------------
extern "C" void kernel_launch(void* const* d_in, const int* in_sizes, int n_in,
                              void* d_out, int out_size) {
    (void)in_sizes; (void)n_in; (void)out_size;
    const float* x  = (const float*)d_in[0];
    const float* Wq = (const float*)d_in[1];
    const float* bq = (const float*)d_in[2];
    const float* Wk = (const float*)d_in[3];
    const float* bk = (const float*)d_in[4];
    const float* Wv = (const float*)d_in[5];
    const float* bv = (const float*)d_in[6];
    float* out = (float*)d_out;

    cudaFuncSetAttribute(gemm128_kernel<1>,
                         cudaFuncAttributeMaxDynamicSharedMemorySize, GEMM_SMEM);

    __half *pXH, *pWTH, *pQH, *pKH, *pVH, *pPH;
    float* pS;
    cudaGetSymbolAddress((void**)&pXH, g_XH);
    cudaGetSymbolAddress((void**)&pWTH, g_WTH);
    cudaGetSymbolAddress((void**)&pQH, g_QH);
    cudaGetSymbolAddress((void**)&pKH, g_KH);
    cudaGetSymbolAddress((void**)&pVH, g_VH);
    cudaGetSymbolAddress((void**)&pPH, g_PH);
    cudaGetSymbolAddress((void**)&pS, g_S);

    dim3 tgrid(128, 128);
    dim3 ggrid(32, 32);

    // x -> fp16 (already K-major for projections)
    cvt_kernel<<<NELEM / 1024, 256>>>((const float4*)x, pXH);

    // q = x @ Wq + bq   (plain fp16)
    transpose_half_kernel<<<tgrid, 256>>>(Wq, pWTH);
    gemm128_kernel<1><<<ggrid, 256, GEMM_SMEM>>>(pXH, pWTH, bq, 1.0f, nullptr, pQH);
    // k = x @ Wk + bk
    transpose_half_kernel<<<tgrid, 256>>>(Wk, pWTH);
    gemm128_kernel<1><<<ggrid, 256, GEMM_SMEM>>>(pXH, pWTH, bk, 1.0f, nullptr, pKH);
    // v = x @ Wv + bv
    transpose_half_kernel<<<tgrid, 256>>>(Wv, pWTH);
    gemm128_kernel<1><<<ggrid, 256, GEMM_SMEM>>>(pXH, pWTH, bv, 1.0f, nullptr, pVH);
    // scores = (q @ k^T) * 1/sqrt(d) -> fp32 g_S
    gemm128_kernel<1><<<ggrid, 256, GEMM_SMEM>>>(pQH, pKH, nullptr, ATT_SCALE, pS, nullptr);
    // P = softmax(scores, rows) -> fp16
    softmax_kernel<<<TDIM, 256>>>(pS, pPH);
    // out[i][j] = sum_m P[i][m] * v[j][m]
    gemm128_kernel<1><<<ggrid, 256, GEMM_SMEM>>>(pPH, pVH, nullptr, 1.0f, out, nullptr);
}